// round 9
// baseline (speedup 1.0000x reference)
#include <cuda_runtime.h>
#include <cuda_bf16.h>
#include <stdint.h>

#define BATCH   2048
#define N0      49
#define CH      768
#define MID     48
#define K1      36
#define K2      24
#define THREADS 768
#define WARPS   24
#define NF4     (N0*CH/4)

// Preprocessed weights (device globals).
//   g_w1t[r][j*CH + c] = bf16( se{r}_w1[c, j] )   transposed -> coalesced GEMV
//   g_w2 [r][j*CH + c] = bf16( se{r}_w2[j, c] )   natural (coalesced per j)
//   g_clsu[o*CH + c]   = ln_gamma[c] * cls_w[c, o]  (fp32, coalesced)
//   g_clsA[o] = sum_c gamma[c]*w[c,o];  g_clsB[o] = sum_c beta[c]*w[c,o] + cls_b[o]
__device__ __nv_bfloat16 g_w1t[2][MID * CH];
__device__ __nv_bfloat16 g_w2 [2][MID * CH];
__device__ float         g_clsu[5 * CH];
__device__ float         g_clsA[5];
__device__ float         g_clsB[5];

__global__ void convert_weights_kernel(const float* __restrict__ w1a,
                                       const float* __restrict__ w2a,
                                       const float* __restrict__ w1b,
                                       const float* __restrict__ w2b,
                                       const float* __restrict__ clsw,
                                       const float* __restrict__ lng,
                                       const float* __restrict__ lnb,
                                       const float* __restrict__ clsb) {
    int i = blockIdx.x * blockDim.x + threadIdx.x;
    if (i < MID * CH) {
        int j = i / CH;
        int c = i - j * CH;
        g_w1t[0][i] = __float2bfloat16(w1a[c * MID + j]);
        g_w1t[1][i] = __float2bfloat16(w1b[c * MID + j]);
        g_w2 [0][i] = __float2bfloat16(w2a[i]);
        g_w2 [1][i] = __float2bfloat16(w2b[i]);
    }
    if (i < 5 * CH) {
        int o = i / CH;
        int c = i - o * CH;
        g_clsu[i] = lng[c] * clsw[c * 5 + o];
    }
    if (i < 5) {
        float A = 0.f, Bv = 0.f;
        for (int c = 0; c < CH; c++) {
            A  += lng[c] * clsw[c * 5 + i];
            Bv += lnb[c] * clsw[c * 5 + i];
        }
        g_clsA[i] = A;
        g_clsB[i] = Bv + clsb[i];
    }
}

// row "energy" partial for one lane: sum over 24 channels of (x*g)^2
__device__ __forceinline__ float row_energy(const float4* __restrict__ row,
                                            const float4* __restrict__ g4p,
                                            int lane) {
    float acc = 0.f;
    #pragma unroll
    for (int k = 0; k < 6; k++) {
        float4 a = row[lane + 32 * k];
        float4 g = g4p[lane + 32 * k];
        float v;
        v = a.x * g.x; acc += v * v;
        v = a.y * g.y; acc += v * v;
        v = a.z * g.z; acc += v * v;
        v = a.w * g.w; acc += v * v;
    }
    return acc;
}

// Shared memory (floats):
//   tile[N0*CH] raw x fp32, part[4*CH], sbuf[CH], csum[CH], gat[CH],
//   hbuf[MID], ts[64], xfin[8], list[40] int, uns[16] int, uns2[16] int
#define SM_FLOATS (N0*CH + 4*CH + CH + CH + CH + MID + 64 + 8 + 40 + 16 + 16)
#define SM_BYTES  (SM_FLOATS * 4)

__global__ __launch_bounds__(THREADS, 1)
void coatgft_kernel(const float* __restrict__ x,
                    const float* __restrict__ b1a, const float* __restrict__ b2a,
                    const float* __restrict__ b1b, const float* __restrict__ b2b,
                    float* __restrict__ out) {
    extern __shared__ float sm[];
    float* tile = sm;                    // [N0*CH]
    float* part = tile + N0 * CH;        // [4*CH]
    float* sbuf = part + 4 * CH;         // [CH]
    float* csum = sbuf + CH;             // [CH]
    float* gat  = csum + CH;             // [CH]
    float* hbuf = gat + CH;              // [MID]
    float* ts   = hbuf + MID;            // [64]
    float* xfin = ts + 64;               // [8]
    int*   list = (int*)(xfin + 8);      // [40]
    int*   uns  = list + 40;             // [16]
    int*   uns2 = uns + 16;              // [16]

    const int tid  = threadIdx.x;
    const int lane = tid & 31;
    const int warp = tid >> 5;
    const int b    = blockIdx.x;

    // ---------- fused load + round-1 column partial sums (R2 pattern) ------
    {
        const float4* __restrict__ xin = (const float4*)(x + (size_t)b * N0 * CH);
        float4* t4 = (float4*)tile;
        float a0 = 0.f, a1 = 0.f, a2 = 0.f, a3 = 0.f;
        #pragma unroll
        for (int k = 0; k < 13; k++) {
            int i = tid + k * THREADS;
            if (i < NF4) {
                float4 v = xin[i];
                t4[i] = v;
                a0 += v.x; a1 += v.y; a2 += v.z; a3 += v.w;
            }
        }
        int c4 = tid % 192;           // float4 column
        int g  = tid / 192;           // row-group 0..3
        float* p = part + g * CH + 4 * c4;
        p[0] = a0; p[1] = a1; p[2] = a2; p[3] = a3;
    }
    __syncthreads();
    {
        float cs = part[tid] + part[CH + tid] + part[2 * CH + tid] + part[3 * CH + tid];
        csum[tid] = cs;
        sbuf[tid] = cs * (1.0f / (float)N0);   // colmean49
    }
    __syncthreads();

    // ================= ROUND 1 =================
    {   // h = gelu(s @ W1 + b1): 2 outputs per warp
        const __nv_bfloat162* W1t = (const __nv_bfloat162*)g_w1t[0];
        #pragma unroll
        for (int jj = 0; jj < 2; jj++) {
            int j = warp + jj * WARPS;
            const __nv_bfloat162* wr = W1t + j * (CH / 2);
            float acc = 0.f;
            #pragma unroll
            for (int k = 0; k < CH / 64; k++) {
                int p = lane + 32 * k;
                __nv_bfloat162 w = wr[p];
                acc += sbuf[2 * p] * __low2float(w) + sbuf[2 * p + 1] * __high2float(w);
            }
            #pragma unroll
            for (int o = 16; o; o >>= 1) acc += __shfl_xor_sync(0xffffffffu, acc, o);
            if (lane == 0) {
                float z = acc + b1a[j];
                hbuf[j] = 0.5f * z * (1.0f + erff(z * 0.70710678118654752f));
            }
        }
    }
    __syncthreads();

    // gates1[c] = sigmoid(h @ W2 + b2)   (coalesced W2, R2 layout)
    {
        const __nv_bfloat16* W2 = g_w2[0];
        float acc = b2a[tid];
        #pragma unroll
        for (int j = 0; j < MID; j++)
            acc += hbuf[j] * __bfloat162float(W2[j * CH + tid]);
        gat[tid] = 1.0f / (1.0f + expf(-acc));
    }
    __syncthreads();

    // ts1[r]: float4 reads, 12 LDS.128 per row
    {
        const float4* g4p = (const float4*)gat;
        #pragma unroll
        for (int ii = 0; ii < 3; ii++) {
            int r = warp + ii * WARPS;
            if (r < N0) {
                float acc = row_energy((const float4*)(tile + r * CH), g4p, lane);
                #pragma unroll
                for (int o = 16; o; o >>= 1) acc += __shfl_xor_sync(0xffffffffu, acc, o);
                if (lane == 0) ts[r] = acc;
            }
        }
    }
    __syncthreads();

    // rank-select top-36 (== jax top_k order); record 13 unselected directly
    if (tid < N0) {
        float mine = ts[tid];
        int r = 0;
        #pragma unroll
        for (int j = 0; j < N0; j++) {
            float tj = ts[j];
            r += (tj > mine) || (tj == mine && j < tid);
        }
        if (r < K1) list[r] = tid;
        else        uns[r - K1] = tid;
    }
    __syncthreads();

    // ================= ROUND 2 =================
    // csum36 = csum49 - 13 unselected rows; s2 = gat*csum36/36
    {
        float cs = csum[tid];
        #pragma unroll
        for (int i = 0; i < N0 - K1; i++) cs -= tile[uns[i] * CH + tid];
        csum[tid] = cs;
        sbuf[tid] = cs * gat[tid] * (1.0f / (float)K1);
    }
    __syncthreads();

    {
        const __nv_bfloat162* W1t = (const __nv_bfloat162*)g_w1t[1];
        #pragma unroll
        for (int jj = 0; jj < 2; jj++) {
            int j = warp + jj * WARPS;
            const __nv_bfloat162* wr = W1t + j * (CH / 2);
            float acc = 0.f;
            #pragma unroll
            for (int k = 0; k < CH / 64; k++) {
                int p = lane + 32 * k;
                __nv_bfloat162 w = wr[p];
                acc += sbuf[2 * p] * __low2float(w) + sbuf[2 * p + 1] * __high2float(w);
            }
            #pragma unroll
            for (int o = 16; o; o >>= 1) acc += __shfl_xor_sync(0xffffffffu, acc, o);
            if (lane == 0) {
                float z = acc + b1b[j];
                hbuf[j] = 0.5f * z * (1.0f + erff(z * 0.70710678118654752f));
            }
        }
    }
    __syncthreads();

    // gat *= gates2
    {
        const __nv_bfloat16* W2 = g_w2[1];
        float acc = b2b[tid];
        #pragma unroll
        for (int j = 0; j < MID; j++)
            acc += hbuf[j] * __bfloat162float(W2[j * CH + tid]);
        gat[tid] *= 1.0f / (1.0f + expf(-acc));
    }
    __syncthreads();

    // ts2 over the 36 selected rows (cumulative gate)
    {
        const float4* g4p = (const float4*)gat;
        #pragma unroll
        for (int ii = 0; ii < 2; ii++) {
            int i = warp + ii * WARPS;
            if (i < K1) {
                float acc = row_energy((const float4*)(tile + list[i] * CH), g4p, lane);
                #pragma unroll
                for (int o = 16; o; o >>= 1) acc += __shfl_xor_sync(0xffffffffu, acc, o);
                if (lane == 0) ts[i] = acc;
            }
        }
    }
    __syncthreads();

    // select top-24 of 36: record the 12 removed rows
    if (tid < K1) {
        float mine = ts[tid];
        int r = 0;
        int row = list[tid];
        #pragma unroll
        for (int j = 0; j < K1; j++) {
            float tj = ts[j];
            r += (tj > mine) || (tj == mine && j < tid);
        }
        if (r >= K2) uns2[r - K2] = row;
    }
    __syncthreads();

    // pooled = gat * (csum36 - 12 removed rows) / 24
    {
        float cs = csum[tid];
        #pragma unroll
        for (int i = 0; i < K1 - K2; i++) cs -= tile[uns2[i] * CH + tid];
        sbuf[tid] = cs * gat[tid] * (1.0f / (float)K2);
    }
    __syncthreads();

    // fused LN+classifier: 7 warp reductions (D0..D4, S1, S2)
    if (warp < 7) {
        float acc = 0.f;
        if (warp < 5) {
            const float* u = g_clsu + warp * CH;
            #pragma unroll
            for (int k = 0; k < CH / 32; k++)
                acc += sbuf[lane + 32 * k] * u[lane + 32 * k];
        } else if (warp == 5) {
            #pragma unroll
            for (int k = 0; k < CH / 32; k++)
                acc += sbuf[lane + 32 * k];
        } else {
            #pragma unroll
            for (int k = 0; k < CH / 32; k++) {
                float v = sbuf[lane + 32 * k];
                acc += v * v;
            }
        }
        #pragma unroll
        for (int o = 16; o; o >>= 1) acc += __shfl_xor_sync(0xffffffffu, acc, o);
        if (lane == 0) xfin[warp] = acc;
    }
    __syncthreads();
    if (tid < 5) {
        float mu  = xfin[5] * (1.0f / (float)CH);
        float var = xfin[6] * (1.0f / (float)CH) - mu * mu;
        float inv = rsqrtf(var + 1e-5f);
        out[b * 5 + tid] = inv * xfin[tid] - inv * mu * g_clsA[tid] + g_clsB[tid];
    }
}

extern "C" void kernel_launch(void* const* d_in, const int* in_sizes, int n_in,
                              void* d_out, int out_size) {
    const float* x    = (const float*)d_in[0];
    const float* w1a  = (const float*)d_in[1];
    const float* b1a  = (const float*)d_in[2];
    const float* w2a  = (const float*)d_in[3];
    const float* b2a  = (const float*)d_in[4];
    const float* w1b  = (const float*)d_in[5];
    const float* b1b  = (const float*)d_in[6];
    const float* w2b  = (const float*)d_in[7];
    const float* b2b  = (const float*)d_in[8];
    const float* lng  = (const float*)d_in[9];
    const float* lnb  = (const float*)d_in[10];
    const float* clsw = (const float*)d_in[11];
    const float* clsb = (const float*)d_in[12];
    float* out = (float*)d_out;

    static_assert(SM_BYTES < 227000, "smem over limit");
    cudaFuncSetAttribute(coatgft_kernel,
                         cudaFuncAttributeMaxDynamicSharedMemorySize, SM_BYTES);

    convert_weights_kernel<<<(MID * CH + 255) / 256, 256>>>(
        w1a, w2a, w1b, w2b, clsw, lng, lnb, clsb);
    coatgft_kernel<<<BATCH, THREADS, SM_BYTES>>>(x, b1a, b2a, b1b, b2b, out);
}

// round 10
// speedup vs baseline: 1.5915x; 1.5915x over previous
#include <cuda_runtime.h>
#include <cuda_bf16.h>

#define BATCH   2048
#define N0      49
#define CH      768
#define MID     48
#define K1      36
#define K2      24
#define THREADS 768
#define WARPS   24
#define NF4     (N0*CH/4)   /* 9408 */

// ---------------------------------------------------------------------------
// Preprocessed weights (device globals; no runtime allocation).  (R2 layout)
//   g_w1t[r][j*CH + c] = bf16( se{r}_w1[c, j] )  transposed -> coalesced GEMV
//   g_w2 [r][j*CH + c] = bf16( se{r}_w2[j, c] )
//   g_clswt[o*CH + c]  = cls_w[c, o]             transposed, fp32
// ---------------------------------------------------------------------------
__device__ __nv_bfloat16 g_w1t[2][MID * CH];
__device__ __nv_bfloat16 g_w2 [2][MID * CH];
__device__ float         g_clswt[5 * CH];

__global__ void convert_weights_kernel(const float* __restrict__ w1a,
                                       const float* __restrict__ w2a,
                                       const float* __restrict__ w1b,
                                       const float* __restrict__ w2b,
                                       const float* __restrict__ clsw) {
    int i = blockIdx.x * blockDim.x + threadIdx.x;
    if (i < MID * CH) {
        int j = i / CH;
        int c = i - j * CH;
        g_w1t[0][i] = __float2bfloat16(w1a[c * MID + j]);
        g_w1t[1][i] = __float2bfloat16(w1b[c * MID + j]);
        g_w2 [0][i] = __float2bfloat16(w2a[i]);
        g_w2 [1][i] = __float2bfloat16(w2b[i]);
    }
    if (i < 5 * CH) {
        int o = i / CH;
        int c = i - o * CH;
        g_clswt[i] = clsw[c * 5 + o];
    }
}

// Shared memory layout (floats)  (R2 + csum + uns/uns2):
//   tile   [N0*CH]  raw x, never modified
//   part   [4*CH]   load-time column partials; later reused for normed vec
//   sbuf   [CH]     SE input vector / pooled
//   csum   [CH]     running column sum (complement trick)
//   gat    [CH]     cumulative gate product
//   hbuf   [MID]
//   ts     [64]
//   list   [64] int,  uns [16] int,  uns2 [16] int
//   red    [64]
#define SM_FLOATS (N0*CH + 4*CH + CH + CH + CH + MID + 64 + 64 + 16 + 16 + 64)
#define SM_BYTES  (SM_FLOATS * 4)

__global__ __launch_bounds__(THREADS, 1)
void coatgft_kernel(const float* __restrict__ x,
                    const float* __restrict__ b1a, const float* __restrict__ b2a,
                    const float* __restrict__ b1b, const float* __restrict__ b2b,
                    const float* __restrict__ ln_g, const float* __restrict__ ln_b,
                    const float* __restrict__ cls_b,
                    float* __restrict__ out) {
    extern __shared__ float sm[];
    float* tile  = sm;
    float* part  = tile + N0 * CH;
    float* sbuf  = part + 4 * CH;
    float* csum  = sbuf + CH;
    float* gat   = csum + CH;
    float* hbuf  = gat + CH;
    float* ts    = hbuf + MID;
    int*   list  = (int*)(ts + 64);
    int*   uns   = list + 64;
    int*   uns2  = uns + 16;
    float* red   = (float*)(uns2 + 16);

    const int tid  = threadIdx.x;
    const int lane = tid & 31;
    const int warp = tid >> 5;
    const int b    = blockIdx.x;

    // ================= load tile + fused round-1 column sums (R2) ===========
    {
        const float4* __restrict__ xin = (const float4*)(x + (size_t)b * N0 * CH);
        float4* t4 = (float4*)tile;
        float a0 = 0.f, a1 = 0.f, a2 = 0.f, a3 = 0.f;
        #pragma unroll
        for (int k = 0; k < 13; k++) {
            int i = tid + k * THREADS;
            if (i < NF4) {
                float4 v = xin[i];
                t4[i] = v;
                a0 += v.x; a1 += v.y; a2 += v.z; a3 += v.w;
            }
        }
        int c4 = tid % 192;           // float4 column
        int g  = tid / 192;           // row-group 0..3
        float* p = part + g * CH + 4 * c4;
        p[0] = a0; p[1] = a1; p[2] = a2; p[3] = a3;
    }
    __syncthreads();

    // s[c] = colmean over 49 rows; keep colsum in csum
    {
        float cs = part[tid] + part[CH + tid] + part[2 * CH + tid] + part[3 * CH + tid];
        csum[tid] = cs;
        sbuf[tid] = cs * (1.0f / (float)N0);
    }
    __syncthreads();

    // ======================= ROUND 1 (49 -> 36) =============================
    {
        const __nv_bfloat16* W1t = g_w1t[0];
        #pragma unroll
        for (int jj = 0; jj < 2; jj++) {
            int j = warp + jj * WARPS;
            const __nv_bfloat16* wr = W1t + j * CH;
            float acc = 0.f;
            #pragma unroll
            for (int c = 0; c < CH / 32; c++)
                acc += sbuf[lane + 32 * c] * __bfloat162float(wr[lane + 32 * c]);
            #pragma unroll
            for (int o = 16; o; o >>= 1) acc += __shfl_xor_sync(0xffffffffu, acc, o);
            if (lane == 0) {
                float z = acc + b1a[j];
                hbuf[j] = 0.5f * z * (1.0f + erff(z * 0.70710678118654752f));
            }
        }
    }
    __syncthreads();

    // gates1[c] = sigmoid(h @ W2 + b2); gat = gates1
    {
        const __nv_bfloat16* W2 = g_w2[0];
        float acc = b2a[tid];
        #pragma unroll
        for (int j = 0; j < MID; j++)
            acc += hbuf[j] * __bfloat162float(W2[j * CH + tid]);
        gat[tid] = 1.0f / (1.0f + expf(-acc));
    }
    __syncthreads();

    // ts[r] = sum_c (x[r][c]*gat[c])^2  (R2 scalar loop)
    #pragma unroll
    for (int ii = 0; ii < 3; ii++) {
        int r = warp + ii * WARPS;
        if (r < N0) {
            const float* row = tile + r * CH;
            float acc = 0.f;
            #pragma unroll
            for (int c = 0; c < CH / 32; c++) {
                float v = row[lane + 32 * c] * gat[lane + 32 * c];
                acc += v * v;
            }
            #pragma unroll
            for (int o = 16; o; o >>= 1) acc += __shfl_xor_sync(0xffffffffu, acc, o);
            if (lane == 0) ts[r] = acc;
        }
    }
    __syncthreads();

    // rank-select top-36 (ties -> lower position, == jax top_k order);
    // write selected rows to list[rank], unselected to uns[rank-K1]
    if (tid < N0) {
        float mine = ts[tid];
        int rank = 0;
        #pragma unroll
        for (int j = 0; j < N0; j++) {
            float tj = ts[j];
            rank += (tj > mine) || (tj == mine && j < tid);
        }
        if (rank < K1) list[rank] = tid;
        else           uns[rank - K1] = tid;
    }
    __syncthreads();

    // ======================= ROUND 2 (36 -> 24) =============================
    // complement: csum36 = csum49 - 13 unselected rows; s2 = gat*csum36/36
    {
        float cs = csum[tid];
        #pragma unroll
        for (int i = 0; i < N0 - K1; i++) cs -= tile[uns[i] * CH + tid];
        csum[tid] = cs;
        sbuf[tid] = cs * gat[tid] * (1.0f / (float)K1);
    }
    __syncthreads();

    {
        const __nv_bfloat16* W1t = g_w1t[1];
        #pragma unroll
        for (int jj = 0; jj < 2; jj++) {
            int j = warp + jj * WARPS;
            const __nv_bfloat16* wr = W1t + j * CH;
            float acc = 0.f;
            #pragma unroll
            for (int c = 0; c < CH / 32; c++)
                acc += sbuf[lane + 32 * c] * __bfloat162float(wr[lane + 32 * c]);
            #pragma unroll
            for (int o = 16; o; o >>= 1) acc += __shfl_xor_sync(0xffffffffu, acc, o);
            if (lane == 0) {
                float z = acc + b1b[j];
                hbuf[j] = 0.5f * z * (1.0f + erff(z * 0.70710678118654752f));
            }
        }
    }
    __syncthreads();

    // gat *= gates2
    {
        const __nv_bfloat16* W2 = g_w2[1];
        float acc = b2b[tid];
        #pragma unroll
        for (int j = 0; j < MID; j++)
            acc += hbuf[j] * __bfloat162float(W2[j * CH + tid]);
        gat[tid] *= 1.0f / (1.0f + expf(-acc));
    }
    __syncthreads();

    // ts over 36 selected rows (cumulative gate), R2 scalar loop
    #pragma unroll
    for (int ii = 0; ii < 2; ii++) {
        int i = warp + ii * WARPS;
        if (i < K1) {
            const float* row = tile + list[i] * CH;
            float acc = 0.f;
            #pragma unroll
            for (int c = 0; c < CH / 32; c++) {
                float v = row[lane + 32 * c] * gat[lane + 32 * c];
                acc += v * v;
            }
            #pragma unroll
            for (int o = 16; o; o >>= 1) acc += __shfl_xor_sync(0xffffffffu, acc, o);
            if (lane == 0) ts[i] = acc;
        }
    }
    __syncthreads();

    // select top-24 of 36: only the 12 REMOVED rows are needed (complement)
    if (tid < K1) {
        float mine = ts[tid];
        int rank = 0;
        int row = list[tid];
        #pragma unroll
        for (int j = 0; j < K1; j++) {
            float tj = ts[j];
            rank += (tj > mine) || (tj == mine && j < tid);
        }
        if (rank >= K2) uns2[rank - K2] = row;
    }
    __syncthreads();

    // ==================== pool + LayerNorm + classifier (R2) ================
    {
        float cs = csum[tid];
        #pragma unroll
        for (int i = 0; i < K1 - K2; i++) cs -= tile[uns2[i] * CH + tid];
        sbuf[tid] = cs * gat[tid] * (1.0f / (float)K2);
    }
    __syncthreads();

    {
        float v = sbuf[tid];
        float p1 = v, p2 = v * v;
        #pragma unroll
        for (int o = 16; o; o >>= 1) {
            p1 += __shfl_xor_sync(0xffffffffu, p1, o);
            p2 += __shfl_xor_sync(0xffffffffu, p2, o);
        }
        if (lane == 0) { red[warp] = p1; red[32 + warp] = p2; }
        __syncthreads();
        if (warp == 0) {
            float m  = (lane < WARPS) ? red[lane]      : 0.f;
            float m2 = (lane < WARPS) ? red[32 + lane] : 0.f;
            #pragma unroll
            for (int o = 16; o; o >>= 1) {
                m  += __shfl_xor_sync(0xffffffffu, m,  o);
                m2 += __shfl_xor_sync(0xffffffffu, m2, o);
            }
            if (lane == 0) {
                m  *= (1.0f / CH);
                m2 *= (1.0f / CH);
                red[60] = m;
                red[61] = rsqrtf(m2 - m * m + 1e-5f);
            }
        }
        __syncthreads();
        float mu = red[60], inv = red[61];
        part[tid] = (v - mu) * inv * ln_g[tid] + ln_b[tid];   // normed
    }
    __syncthreads();

    if (warp < 5) {
        const float* wr = g_clswt + warp * CH;
        float acc = 0.f;
        #pragma unroll
        for (int c = 0; c < CH / 32; c++)
            acc += part[lane + 32 * c] * wr[lane + 32 * c];
        #pragma unroll
        for (int o = 16; o; o >>= 1) acc += __shfl_xor_sync(0xffffffffu, acc, o);
        if (lane == 0) out[b * 5 + warp] = acc + cls_b[warp];
    }
}

extern "C" void kernel_launch(void* const* d_in, const int* in_sizes, int n_in,
                              void* d_out, int out_size) {
    const float* x    = (const float*)d_in[0];
    const float* w1a  = (const float*)d_in[1];
    const float* b1a  = (const float*)d_in[2];
    const float* w2a  = (const float*)d_in[3];
    const float* b2a  = (const float*)d_in[4];
    const float* w1b  = (const float*)d_in[5];
    const float* b1b  = (const float*)d_in[6];
    const float* w2b  = (const float*)d_in[7];
    const float* b2b  = (const float*)d_in[8];
    const float* lng  = (const float*)d_in[9];
    const float* lnb  = (const float*)d_in[10];
    const float* clsw = (const float*)d_in[11];
    const float* clsb = (const float*)d_in[12];
    float* out = (float*)d_out;

    static_assert(SM_BYTES < 227000, "smem over limit");
    cudaFuncSetAttribute(coatgft_kernel,
                         cudaFuncAttributeMaxDynamicSharedMemorySize, SM_BYTES);

    convert_weights_kernel<<<(MID * CH + 255) / 256, 256>>>(w1a, w2a, w1b, w2b, clsw);
    coatgft_kernel<<<BATCH, THREADS, SM_BYTES>>>(x, b1a, b2a, b1b, b2b,
                                                 lng, lnb, clsb, out);
}

// round 11
// speedup vs baseline: 1.5927x; 1.0007x over previous
#include <cuda_runtime.h>
#include <cuda_bf16.h>

#define BATCH   2048
#define N0      49
#define CH      768
#define MID     48
#define K1      36
#define K2      24
#define THREADS 768
#define WARPS   24
#define NF4     (N0*CH/4)   /* 9408 */

// ---------------------------------------------------------------------------
// Preprocessed weights (device globals; no runtime allocation).  (R2 layout)
//   g_w1t[r][j*CH + c] = bf16( se{r}_w1[c, j] )  transposed -> coalesced GEMV
//   g_w2 [r][j*CH + c] = bf16( se{r}_w2[j, c] )
//   g_clswt[o*CH + c]  = cls_w[c, o]             transposed, fp32
// ---------------------------------------------------------------------------
__device__ __nv_bfloat16 g_w1t[2][MID * CH];
__device__ __nv_bfloat16 g_w2 [2][MID * CH];
__device__ float         g_clswt[5 * CH];

__global__ void convert_weights_kernel(const float* __restrict__ w1a,
                                       const float* __restrict__ w2a,
                                       const float* __restrict__ w1b,
                                       const float* __restrict__ w2b,
                                       const float* __restrict__ clsw) {
    int i = blockIdx.x * blockDim.x + threadIdx.x;
    if (i < MID * CH) {
        int j = i / CH;
        int c = i - j * CH;
        g_w1t[0][i] = __float2bfloat16(w1a[c * MID + j]);
        g_w1t[1][i] = __float2bfloat16(w1b[c * MID + j]);
        g_w2 [0][i] = __float2bfloat16(w2a[i]);
        g_w2 [1][i] = __float2bfloat16(w2b[i]);
    }
    if (i < 5 * CH) {
        int o = i / CH;
        int c = i - o * CH;
        g_clswt[i] = clsw[c * 5 + o];
    }
}

// ts row partial: 6x float4 tile + gate loads per lane (LDS.128)
__device__ __forceinline__ float row_energy4(const float4* __restrict__ row,
                                             const float4* __restrict__ g4p,
                                             int lane) {
    float acc = 0.f;
    #pragma unroll
    for (int k = 0; k < 6; k++) {
        float4 a = row[lane + 32 * k];
        float4 g = g4p[lane + 32 * k];
        float v;
        v = a.x * g.x; acc += v * v;
        v = a.y * g.y; acc += v * v;
        v = a.z * g.z; acc += v * v;
        v = a.w * g.w; acc += v * v;
    }
    return acc;
}

// Shared memory layout (floats)  (identical to R10):
#define SM_FLOATS (N0*CH + 4*CH + CH + CH + CH + MID + 64 + 64 + 16 + 16 + 64)
#define SM_BYTES  (SM_FLOATS * 4)

__global__ __launch_bounds__(THREADS, 1)
void coatgft_kernel(const float* __restrict__ x,
                    const float* __restrict__ b1a, const float* __restrict__ b2a,
                    const float* __restrict__ b1b, const float* __restrict__ b2b,
                    const float* __restrict__ ln_g, const float* __restrict__ ln_b,
                    const float* __restrict__ cls_b,
                    float* __restrict__ out) {
    extern __shared__ float sm[];
    float* tile  = sm;
    float* part  = tile + N0 * CH;
    float* sbuf  = part + 4 * CH;
    float* csum  = sbuf + CH;
    float* gat   = csum + CH;
    float* hbuf  = gat + CH;
    float* ts    = hbuf + MID;
    int*   list  = (int*)(ts + 64);
    int*   uns   = list + 64;
    int*   uns2  = uns + 16;
    float* red   = (float*)(uns2 + 16);

    const int tid  = threadIdx.x;
    const int lane = tid & 31;
    const int warp = tid >> 5;
    const int b    = blockIdx.x;

    // ================= load tile + fused round-1 column sums (R2) ===========
    {
        const float4* __restrict__ xin = (const float4*)(x + (size_t)b * N0 * CH);
        float4* t4 = (float4*)tile;
        float a0 = 0.f, a1 = 0.f, a2 = 0.f, a3 = 0.f;
        #pragma unroll
        for (int k = 0; k < 13; k++) {
            int i = tid + k * THREADS;
            if (i < NF4) {
                float4 v = xin[i];
                t4[i] = v;
                a0 += v.x; a1 += v.y; a2 += v.z; a3 += v.w;
            }
        }
        int c4 = tid % 192;           // float4 column
        int g  = tid / 192;           // row-group 0..3
        float* p = part + g * CH + 4 * c4;
        p[0] = a0; p[1] = a1; p[2] = a2; p[3] = a3;
    }
    __syncthreads();

    // s[c] = colmean over 49 rows; keep colsum in csum
    {
        float cs = part[tid] + part[CH + tid] + part[2 * CH + tid] + part[3 * CH + tid];
        csum[tid] = cs;
        sbuf[tid] = cs * (1.0f / (float)N0);
    }
    __syncthreads();

    // ======================= ROUND 1 (49 -> 36) =============================
    {
        const __nv_bfloat16* W1t = g_w1t[0];
        #pragma unroll
        for (int jj = 0; jj < 2; jj++) {
            int j = warp + jj * WARPS;
            const __nv_bfloat16* wr = W1t + j * CH;
            float acc = 0.f;
            #pragma unroll
            for (int c = 0; c < CH / 32; c++)
                acc += sbuf[lane + 32 * c] * __bfloat162float(wr[lane + 32 * c]);
            #pragma unroll
            for (int o = 16; o; o >>= 1) acc += __shfl_xor_sync(0xffffffffu, acc, o);
            if (lane == 0) {
                float z = acc + b1a[j];
                hbuf[j] = 0.5f * z * (1.0f + erff(z * 0.70710678118654752f));
            }
        }
    }
    __syncthreads();

    // gates1[c] = sigmoid(h @ W2 + b2); gat = gates1
    {
        const __nv_bfloat16* W2 = g_w2[0];
        float acc = b2a[tid];
        #pragma unroll
        for (int j = 0; j < MID; j++)
            acc += hbuf[j] * __bfloat162float(W2[j * CH + tid]);
        gat[tid] = 1.0f / (1.0f + expf(-acc));
    }
    __syncthreads();

    // ts[r] = sum_c (x[r][c]*gat[c])^2   (float4 LDS.128 version)
    {
        const float4* g4p = (const float4*)gat;
        #pragma unroll
        for (int ii = 0; ii < 3; ii++) {
            int r = warp + ii * WARPS;
            if (r < N0) {
                float acc = row_energy4((const float4*)(tile + r * CH), g4p, lane);
                #pragma unroll
                for (int o = 16; o; o >>= 1) acc += __shfl_xor_sync(0xffffffffu, acc, o);
                if (lane == 0) ts[r] = acc;
            }
        }
    }
    __syncthreads();

    // rank-select top-36 (ties -> lower position, == jax top_k order)
    if (tid < N0) {
        float mine = ts[tid];
        int rank = 0;
        #pragma unroll
        for (int j = 0; j < N0; j++) {
            float tj = ts[j];
            rank += (tj > mine) || (tj == mine && j < tid);
        }
        if (rank < K1) list[rank] = tid;
        else           uns[rank - K1] = tid;
    }
    __syncthreads();

    // ======================= ROUND 2 (36 -> 24) =============================
    // complement: csum36 = csum49 - 13 unselected rows; s2 = gat*csum36/36
    {
        float cs = csum[tid];
        #pragma unroll
        for (int i = 0; i < N0 - K1; i++) cs -= tile[uns[i] * CH + tid];
        csum[tid] = cs;
        sbuf[tid] = cs * gat[tid] * (1.0f / (float)K1);
    }
    __syncthreads();

    {
        const __nv_bfloat16* W1t = g_w1t[1];
        #pragma unroll
        for (int jj = 0; jj < 2; jj++) {
            int j = warp + jj * WARPS;
            const __nv_bfloat16* wr = W1t + j * CH;
            float acc = 0.f;
            #pragma unroll
            for (int c = 0; c < CH / 32; c++)
                acc += sbuf[lane + 32 * c] * __bfloat162float(wr[lane + 32 * c]);
            #pragma unroll
            for (int o = 16; o; o >>= 1) acc += __shfl_xor_sync(0xffffffffu, acc, o);
            if (lane == 0) {
                float z = acc + b1b[j];
                hbuf[j] = 0.5f * z * (1.0f + erff(z * 0.70710678118654752f));
            }
        }
    }
    __syncthreads();

    // gat *= gates2
    {
        const __nv_bfloat16* W2 = g_w2[1];
        float acc = b2b[tid];
        #pragma unroll
        for (int j = 0; j < MID; j++)
            acc += hbuf[j] * __bfloat162float(W2[j * CH + tid]);
        gat[tid] *= 1.0f / (1.0f + expf(-acc));
    }
    __syncthreads();

    // ts over 36 selected rows (cumulative gate), float4 version
    {
        const float4* g4p = (const float4*)gat;
        #pragma unroll
        for (int ii = 0; ii < 2; ii++) {
            int i = warp + ii * WARPS;
            if (i < K1) {
                float acc = row_energy4((const float4*)(tile + list[i] * CH), g4p, lane);
                #pragma unroll
                for (int o = 16; o; o >>= 1) acc += __shfl_xor_sync(0xffffffffu, acc, o);
                if (lane == 0) ts[i] = acc;
            }
        }
    }
    __syncthreads();

    // select top-24 of 36: only the 12 REMOVED rows needed (complement)
    if (tid < K1) {
        float mine = ts[tid];
        int rank = 0;
        int row = list[tid];
        #pragma unroll
        for (int j = 0; j < K1; j++) {
            float tj = ts[j];
            rank += (tj > mine) || (tj == mine && j < tid);
        }
        if (rank >= K2) uns2[rank - K2] = row;
    }
    __syncthreads();

    // ==================== pool + LayerNorm + classifier (R2) ================
    {
        float cs = csum[tid];
        #pragma unroll
        for (int i = 0; i < K1 - K2; i++) cs -= tile[uns2[i] * CH + tid];
        sbuf[tid] = cs * gat[tid] * (1.0f / (float)K2);
    }
    __syncthreads();

    {
        float v = sbuf[tid];
        float p1 = v, p2 = v * v;
        #pragma unroll
        for (int o = 16; o; o >>= 1) {
            p1 += __shfl_xor_sync(0xffffffffu, p1, o);
            p2 += __shfl_xor_sync(0xffffffffu, p2, o);
        }
        if (lane == 0) { red[warp] = p1; red[32 + warp] = p2; }
        __syncthreads();
        if (warp == 0) {
            float m  = (lane < WARPS) ? red[lane]      : 0.f;
            float m2 = (lane < WARPS) ? red[32 + lane] : 0.f;
            #pragma unroll
            for (int o = 16; o; o >>= 1) {
                m  += __shfl_xor_sync(0xffffffffu, m,  o);
                m2 += __shfl_xor_sync(0xffffffffu, m2, o);
            }
            if (lane == 0) {
                m  *= (1.0f / CH);
                m2 *= (1.0f / CH);
                red[60] = m;
                red[61] = rsqrtf(m2 - m * m + 1e-5f);
            }
        }
        __syncthreads();
        float mu = red[60], inv = red[61];
        part[tid] = (v - mu) * inv * ln_g[tid] + ln_b[tid];   // normed
    }
    __syncthreads();

    if (warp < 5) {
        const float* wr = g_clswt + warp * CH;
        float acc = 0.f;
        #pragma unroll
        for (int c = 0; c < CH / 32; c++)
            acc += part[lane + 32 * c] * wr[lane + 32 * c];
        #pragma unroll
        for (int o = 16; o; o >>= 1) acc += __shfl_xor_sync(0xffffffffu, acc, o);
        if (lane == 0) out[b * 5 + warp] = acc + cls_b[warp];
    }
}

extern "C" void kernel_launch(void* const* d_in, const int* in_sizes, int n_in,
                              void* d_out, int out_size) {
    const float* x    = (const float*)d_in[0];
    const float* w1a  = (const float*)d_in[1];
    const float* b1a  = (const float*)d_in[2];
    const float* w2a  = (const float*)d_in[3];
    const float* b2a  = (const float*)d_in[4];
    const float* w1b  = (const float*)d_in[5];
    const float* b1b  = (const float*)d_in[6];
    const float* w2b  = (const float*)d_in[7];
    const float* b2b  = (const float*)d_in[8];
    const float* lng  = (const float*)d_in[9];
    const float* lnb  = (const float*)d_in[10];
    const float* clsw = (const float*)d_in[11];
    const float* clsb = (const float*)d_in[12];
    float* out = (float*)d_out;

    static_assert(SM_BYTES < 227000, "smem over limit");
    cudaFuncSetAttribute(coatgft_kernel,
                         cudaFuncAttributeMaxDynamicSharedMemorySize, SM_BYTES);

    convert_weights_kernel<<<(MID * CH + 255) / 256, 256>>>(w1a, w2a, w1b, w2b, clsw);
    coatgft_kernel<<<BATCH, THREADS, SM_BYTES>>>(x, b1a, b2a, b1b, b2b,
                                                 lng, lnb, clsb, out);
}

// round 12
// speedup vs baseline: 2.2977x; 1.4427x over previous
#include <cuda_runtime.h>
#include <cuda_bf16.h>

#define BATCH   2048
#define N0      49
#define CH      768
#define MID     48
#define K1      36
#define K2      24
#define THREADS 256
#define WARPS   8

// Preprocessed weights (device globals). R2/R10 layouts.
//   g_w1t[r][j*CH + c] = bf16( se{r}_w1[c, j] )
//   g_w2 [r][j*CH + c] = bf16( se{r}_w2[j, c] )
//   g_clswt[o*CH + c]  = cls_w[c, o]  fp32
__device__ __nv_bfloat16 g_w1t[2][MID * CH];
__device__ __nv_bfloat16 g_w2 [2][MID * CH];
__device__ float         g_clswt[5 * CH];

__global__ void convert_weights_kernel(const float* __restrict__ w1a,
                                       const float* __restrict__ w2a,
                                       const float* __restrict__ w1b,
                                       const float* __restrict__ w2b,
                                       const float* __restrict__ clsw) {
    int i = blockIdx.x * blockDim.x + threadIdx.x;
    if (i < MID * CH) {
        int j = i / CH;
        int c = i - j * CH;
        g_w1t[0][i] = __float2bfloat16(w1a[c * MID + j]);
        g_w1t[1][i] = __float2bfloat16(w1b[c * MID + j]);
        g_w2 [0][i] = __float2bfloat16(w2a[i]);
        g_w2 [1][i] = __float2bfloat16(w2b[i]);
    }
    if (i < 5 * CH) {
        int o = i / CH;
        int c = i - o * CH;
        g_clswt[i] = clsw[c * 5 + o];
    }
}

// Shared memory (floats): sbuf[CH], csum[CH], gat[CH], hbuf[MID],
// ts[64], list[40] int, uns[16] int, uns2[16] int, red[80]
#define SM_FLOATS (CH + CH + CH + MID + 64 + 40 + 16 + 16 + 80)
#define SM_BYTES  (SM_FLOATS * 4)

__global__ __launch_bounds__(THREADS, 4)
void coatgft_kernel(const float* __restrict__ x,
                    const float* __restrict__ b1a, const float* __restrict__ b2a,
                    const float* __restrict__ b1b, const float* __restrict__ b2b,
                    const float* __restrict__ ln_g, const float* __restrict__ ln_b,
                    const float* __restrict__ cls_b,
                    float* __restrict__ out) {
    extern __shared__ float sm[];
    float* sbuf = sm;                    // [CH]
    float* csum = sbuf + CH;             // [CH]
    float* gat  = csum + CH;             // [CH]
    float* hbuf = gat + CH;              // [MID]
    float* ts   = hbuf + MID;            // [64]
    int*   list = (int*)(ts + 64);       // [40]
    int*   uns  = list + 40;             // [16]
    int*   uns2 = uns + 16;              // [16]
    float* red  = (float*)(uns2 + 16);   // [80]

    const int tid  = threadIdx.x;
    const int lane = tid & 31;
    const int warp = tid >> 5;
    const int b    = blockIdx.x;
    const float* __restrict__ xb = x + (size_t)b * N0 * CH;

    // ---- 1. colmean + colsum over 49 rows: 3 channels per thread (L2-only) --
    {
        float a0 = 0.f, a1 = 0.f, a2 = 0.f;
        #pragma unroll 7
        for (int r = 0; r < N0; r++) {
            const float* row = xb + (size_t)r * CH;
            a0 += __ldcg(row + tid);
            a1 += __ldcg(row + tid + 256);
            a2 += __ldcg(row + tid + 512);
        }
        csum[tid]       = a0;  sbuf[tid]       = a0 * (1.0f / (float)N0);
        csum[tid + 256] = a1;  sbuf[tid + 256] = a1 * (1.0f / (float)N0);
        csum[tid + 512] = a2;  sbuf[tid + 512] = a2 * (1.0f / (float)N0);
    }
    __syncthreads();

    // ======================= ROUND 1 (49 -> 36) =============================
    {   // h = gelu(s @ W1 + b1): 6 outputs per warp
        const __nv_bfloat162* W1t = (const __nv_bfloat162*)g_w1t[0];
        #pragma unroll
        for (int jj = 0; jj < 6; jj++) {
            int j = warp + jj * WARPS;
            const __nv_bfloat162* wr = W1t + j * (CH / 2);
            float acc = 0.f;
            #pragma unroll
            for (int k = 0; k < CH / 64; k++) {
                int p = lane + 32 * k;
                __nv_bfloat162 w = wr[p];
                acc += sbuf[2 * p] * __low2float(w) + sbuf[2 * p + 1] * __high2float(w);
            }
            #pragma unroll
            for (int o = 16; o; o >>= 1) acc += __shfl_xor_sync(0xffffffffu, acc, o);
            if (lane == 0) {
                float z = acc + b1a[j];
                hbuf[j] = 0.5f * z * (1.0f + erff(z * 0.70710678118654752f));
            }
        }
    }
    __syncthreads();

    // gates1: 3 channels per thread (W2 coalesced, L1-resident)
    {
        const __nv_bfloat16* W2 = g_w2[0];
        float a0 = b2a[tid], a1 = b2a[tid + 256], a2 = b2a[tid + 512];
        #pragma unroll
        for (int j = 0; j < MID; j++) {
            float h = hbuf[j];
            const __nv_bfloat16* wj = W2 + j * CH;
            a0 += h * __bfloat162float(wj[tid]);
            a1 += h * __bfloat162float(wj[tid + 256]);
            a2 += h * __bfloat162float(wj[tid + 512]);
        }
        gat[tid]       = 1.0f / (1.0f + expf(-a0));
        gat[tid + 256] = 1.0f / (1.0f + expf(-a1));
        gat[tid + 512] = 1.0f / (1.0f + expf(-a2));
    }
    __syncthreads();

    // ts1[r] = sum_c (x*g)^2: warp per row, x from L2 (float4), g from smem
    {
        const float4* g4p = (const float4*)gat;
        #pragma unroll
        for (int ii = 0; ii < 7; ii++) {
            int r = warp + ii * WARPS;
            if (r < N0) {
                const float4* row = (const float4*)(xb + (size_t)r * CH);
                float acc = 0.f;
                #pragma unroll
                for (int k = 0; k < 6; k++) {
                    float4 a = __ldcg(row + lane + 32 * k);
                    float4 g = g4p[lane + 32 * k];
                    float v;
                    v = a.x * g.x; acc += v * v;
                    v = a.y * g.y; acc += v * v;
                    v = a.z * g.z; acc += v * v;
                    v = a.w * g.w; acc += v * v;
                }
                #pragma unroll
                for (int o = 16; o; o >>= 1) acc += __shfl_xor_sync(0xffffffffu, acc, o);
                if (lane == 0) ts[r] = acc;
            }
        }
    }
    __syncthreads();

    // rank-select top-36 (== jax top_k order); 13 unselected to uns
    if (tid < N0) {
        float mine = ts[tid];
        int rank = 0;
        #pragma unroll
        for (int j = 0; j < N0; j++) {
            float tj = ts[j];
            rank += (tj > mine) || (tj == mine && j < tid);
        }
        if (rank < K1) list[rank] = tid;
        else           uns[rank - K1] = tid;
    }
    __syncthreads();

    // ======================= ROUND 2 (36 -> 24) =============================
    // csum36 = csum49 - 13 unselected rows (L2 reads); s2 = gat*csum36/36
    {
        float c0 = csum[tid], c1 = csum[tid + 256], c2 = csum[tid + 512];
        #pragma unroll
        for (int i = 0; i < N0 - K1; i++) {
            const float* row = xb + (size_t)uns[i] * CH;
            c0 -= __ldcg(row + tid);
            c1 -= __ldcg(row + tid + 256);
            c2 -= __ldcg(row + tid + 512);
        }
        csum[tid] = c0;       sbuf[tid]       = c0 * gat[tid]       * (1.0f / (float)K1);
        csum[tid + 256] = c1; sbuf[tid + 256] = c1 * gat[tid + 256] * (1.0f / (float)K1);
        csum[tid + 512] = c2; sbuf[tid + 512] = c2 * gat[tid + 512] * (1.0f / (float)K1);
    }
    __syncthreads();

    {
        const __nv_bfloat162* W1t = (const __nv_bfloat162*)g_w1t[1];
        #pragma unroll
        for (int jj = 0; jj < 6; jj++) {
            int j = warp + jj * WARPS;
            const __nv_bfloat162* wr = W1t + j * (CH / 2);
            float acc = 0.f;
            #pragma unroll
            for (int k = 0; k < CH / 64; k++) {
                int p = lane + 32 * k;
                __nv_bfloat162 w = wr[p];
                acc += sbuf[2 * p] * __low2float(w) + sbuf[2 * p + 1] * __high2float(w);
            }
            #pragma unroll
            for (int o = 16; o; o >>= 1) acc += __shfl_xor_sync(0xffffffffu, acc, o);
            if (lane == 0) {
                float z = acc + b1b[j];
                hbuf[j] = 0.5f * z * (1.0f + erff(z * 0.70710678118654752f));
            }
        }
    }
    __syncthreads();

    // gat *= gates2
    {
        const __nv_bfloat16* W2 = g_w2[1];
        float a0 = b2b[tid], a1 = b2b[tid + 256], a2 = b2b[tid + 512];
        #pragma unroll
        for (int j = 0; j < MID; j++) {
            float h = hbuf[j];
            const __nv_bfloat16* wj = W2 + j * CH;
            a0 += h * __bfloat162float(wj[tid]);
            a1 += h * __bfloat162float(wj[tid + 256]);
            a2 += h * __bfloat162float(wj[tid + 512]);
        }
        gat[tid]       *= 1.0f / (1.0f + expf(-a0));
        gat[tid + 256] *= 1.0f / (1.0f + expf(-a1));
        gat[tid + 512] *= 1.0f / (1.0f + expf(-a2));
    }
    __syncthreads();

    // ts2 over 36 selected rows (cumulative gate)
    {
        const float4* g4p = (const float4*)gat;
        #pragma unroll
        for (int ii = 0; ii < 5; ii++) {
            int i = warp + ii * WARPS;
            if (i < K1) {
                const float4* row = (const float4*)(xb + (size_t)list[i] * CH);
                float acc = 0.f;
                #pragma unroll
                for (int k = 0; k < 6; k++) {
                    float4 a = __ldcg(row + lane + 32 * k);
                    float4 g = g4p[lane + 32 * k];
                    float v;
                    v = a.x * g.x; acc += v * v;
                    v = a.y * g.y; acc += v * v;
                    v = a.z * g.z; acc += v * v;
                    v = a.w * g.w; acc += v * v;
                }
                #pragma unroll
                for (int o = 16; o; o >>= 1) acc += __shfl_xor_sync(0xffffffffu, acc, o);
                if (lane == 0) ts[i] = acc;
            }
        }
    }
    __syncthreads();

    // top-24 of 36: record the 12 removed rows
    if (tid < K1) {
        float mine = ts[tid];
        int rank = 0;
        int row = list[tid];
        #pragma unroll
        for (int j = 0; j < K1; j++) {
            float tj = ts[j];
            rank += (tj > mine) || (tj == mine && j < tid);
        }
        if (rank >= K2) uns2[rank - K2] = row;
    }
    __syncthreads();

    // pooled = gat * (csum36 - 12 removed rows) / 24
    {
        float c0 = csum[tid], c1 = csum[tid + 256], c2 = csum[tid + 512];
        #pragma unroll
        for (int i = 0; i < K1 - K2; i++) {
            const float* row = xb + (size_t)uns2[i] * CH;
            c0 -= __ldcg(row + tid);
            c1 -= __ldcg(row + tid + 256);
            c2 -= __ldcg(row + tid + 512);
        }
        sbuf[tid]       = c0 * gat[tid]       * (1.0f / (float)K2);
        sbuf[tid + 256] = c1 * gat[tid + 256] * (1.0f / (float)K2);
        sbuf[tid + 512] = c2 * gat[tid + 512] * (1.0f / (float)K2);
    }
    __syncthreads();

    // ---- LayerNorm stats ----
    {
        float v0 = sbuf[tid], v1 = sbuf[tid + 256], v2 = sbuf[tid + 512];
        float p1 = v0 + v1 + v2;
        float p2 = v0 * v0 + v1 * v1 + v2 * v2;
        #pragma unroll
        for (int o = 16; o; o >>= 1) {
            p1 += __shfl_xor_sync(0xffffffffu, p1, o);
            p2 += __shfl_xor_sync(0xffffffffu, p2, o);
        }
        if (lane == 0) { red[warp] = p1; red[8 + warp] = p2; }
        __syncthreads();
        if (warp == 0) {
            float m  = (lane < WARPS) ? red[lane]     : 0.f;
            float m2 = (lane < WARPS) ? red[8 + lane] : 0.f;
            #pragma unroll
            for (int o = 4; o; o >>= 1) {
                m  += __shfl_xor_sync(0xffffffffu, m,  o);
                m2 += __shfl_xor_sync(0xffffffffu, m2, o);
            }
            if (lane == 0) {
                m  *= (1.0f / CH);
                m2 *= (1.0f / CH);
                red[16] = m;
                red[17] = rsqrtf(m2 - m * m + 1e-5f);
            }
        }
        __syncthreads();
        float mu = red[16], inv = red[17];
        gat[tid]       = (sbuf[tid]       - mu) * inv * ln_g[tid]       + ln_b[tid];
        gat[tid + 256] = (sbuf[tid + 256] - mu) * inv * ln_g[tid + 256] + ln_b[tid + 256];
        gat[tid + 512] = (sbuf[tid + 512] - mu) * inv * ln_g[tid + 512] + ln_b[tid + 512];
    }
    __syncthreads();

    // ---- classifier: 5 outputs, one warp each ----
    if (warp < 5) {
        const float* wr = g_clswt + warp * CH;
        float acc = 0.f;
        #pragma unroll
        for (int k = 0; k < CH / 32; k++)
            acc += gat[lane + 32 * k] * wr[lane + 32 * k];
        #pragma unroll
        for (int o = 16; o; o >>= 1) acc += __shfl_xor_sync(0xffffffffu, acc, o);
        if (lane == 0) out[b * 5 + warp] = acc + cls_b[warp];
    }
}

extern "C" void kernel_launch(void* const* d_in, const int* in_sizes, int n_in,
                              void* d_out, int out_size) {
    const float* x    = (const float*)d_in[0];
    const float* w1a  = (const float*)d_in[1];
    const float* b1a  = (const float*)d_in[2];
    const float* w2a  = (const float*)d_in[3];
    const float* b2a  = (const float*)d_in[4];
    const float* w1b  = (const float*)d_in[5];
    const float* b1b  = (const float*)d_in[6];
    const float* w2b  = (const float*)d_in[7];
    const float* b2b  = (const float*)d_in[8];
    const float* lng  = (const float*)d_in[9];
    const float* lnb  = (const float*)d_in[10];
    const float* clsw = (const float*)d_in[11];
    const float* clsb = (const float*)d_in[12];
    float* out = (float*)d_out;

    cudaFuncSetAttribute(coatgft_kernel,
                         cudaFuncAttributeMaxDynamicSharedMemorySize, SM_BYTES);

    convert_weights_kernel<<<(MID * CH + 255) / 256, 256>>>(w1a, w2a, w1b, w2b, clsw);
    coatgft_kernel<<<BATCH, THREADS, SM_BYTES>>>(x, b1a, b2a, b1b, b2b,
                                                 lng, lnb, clsb, out);
}